// round 16
// baseline (speedup 1.0000x reference)
#include <cuda_runtime.h>
#include <cuda_fp16.h>
#include <cstdint>

typedef unsigned long long ull;
#define MAXN 100096
#define MAXE 1700000

__device__ float  g_AX[MAXN*128];
__device__ __half g_Xh[MAXN*128];
__device__ ull    g_keys [MAXN];
__device__ ull    g_candA[MAXN];
__device__ ull    g_candB[MAXN];
__device__ float  g_wev[128*128];
__device__ float  g_dinv[MAXN];
__device__ int    g_cnt [MAXN];
__device__ int    g_off [MAXN+1];
__device__ int    g_cur [MAXN];
__device__ int    g_rows[MAXE];
__device__ int    g_bsum[256];
__device__ int    g_boff[256];
__device__ float  g_pinv;
__device__ int    g_e64;

__device__ __forceinline__ int edge_at(const void* edge, size_t idx){
    return g_e64 ? ((const int*)edge)[2*idx] : ((const int*)edge)[idx];
}

// ---- tf32 helpers ----------------------------------------------------------
__device__ __forceinline__ unsigned f2tf(float x){
    unsigned r; asm("cvt.rna.tf32.f32 %0, %1;" : "=r"(r) : "f"(x)); return r;
}
__device__ __forceinline__ void mma_tf32(float* c, const unsigned* a, unsigned b0, unsigned b1){
    asm volatile("mma.sync.aligned.m16n8k8.row.col.f32.tf32.tf32.f32 "
        "{%0,%1,%2,%3},{%4,%5,%6,%7},{%8,%9},{%0,%1,%2,%3};"
        : "+f"(c[0]),"+f"(c[1]),"+f"(c[2]),"+f"(c[3])
        : "r"(a[0]),"r"(a[1]),"r"(a[2]),"r"(a[3]), "r"(b0),"r"(b1));
}

// ---- setup (pnorm + dtype detect) fused with cnt zeroing -------------------
__global__ void setup_zero(const void* __restrict__ edge, const float* __restrict__ p, int N){
    __shared__ float s[128];
    int i = blockIdx.x*256 + threadIdx.x;
    if (i < N) g_cnt[i] = 0;
    if (blockIdx.x == 0){
        int t = threadIdx.x;
        if (t < 128){ float v = p[t]; s[t] = v*v; }
        __syncthreads();
        for (int o=64;o>0;o>>=1){ if (t<o) s[t]+=s[t+o]; __syncthreads(); }
        if (t==0){
            g_pinv = rsqrtf(s[0]);
            const long long* e = (const long long*)edge;
            int ok = 1;
            for (int k=0;k<8;k++){ long long vv=e[k]; if (vv<0 || vv>=(long long)N) ok=0; }
            g_e64 = ok;
        }
    }
}

// ---- scans -----------------------------------------------------------------
__global__ void scan1(int N){
    __shared__ int s[512];
    int t = threadIdx.x;
    int i = blockIdx.x*512 + t;
    int v = (i<N) ? g_cnt[i] : 0;
    if (i<N) g_dinv[i] = rsqrtf((float)(v+1));
    s[t]=v; __syncthreads();
    for (int o=1;o<512;o<<=1){
        int tmp = (t>=o)? s[t-o] : 0; __syncthreads();
        s[t]+=tmp; __syncthreads();
    }
    if (i<N) g_off[i] = s[t]-v;
    if (t==511) g_bsum[blockIdx.x] = s[511];
}
__global__ void scan2(int nb){
    __shared__ int s[256];
    int t=threadIdx.x;
    int v = (t<nb)? g_bsum[t] : 0;
    s[t]=v; __syncthreads();
    for (int o=1;o<256;o<<=1){
        int tmp=(t>=o)?s[t-o]:0; __syncthreads();
        s[t]+=tmp; __syncthreads();
    }
    g_boff[t] = s[t]-v;
}
__global__ void scan3(int N, int E){
    int i = blockIdx.x*blockDim.x + threadIdx.x;
    if (i<N){
        int v = g_off[i] + g_boff[i>>9];
        g_off[i]=v; g_cur[i]=v;
    }
    if (i==0) g_off[N]=E;
}

// ---- FAT1: blocks [0,nbG) = 3xTF32 GEMM1 + fused scores; rest = cnt_count --
__global__ __launch_bounds__(256) void fat1(const float* __restrict__ A,
                                            const float* __restrict__ B,
                                            const float* __restrict__ bias,
                                            const float* __restrict__ p,
                                            float* __restrict__ outh,
                                            const void* __restrict__ edge,
                                            int N, int E, int nbG){
    if (blockIdx.x >= nbG){
        int e = (blockIdx.x - nbG)*256 + threadIdx.x;
        if (e < E) atomicAdd(&g_cnt[edge_at(edge,(size_t)E+e)],1);
        return;
    }
    __shared__ float sAhi[128*20], sAlo[128*20];
    __shared__ float sBhi[16*132], sBlo[16*132];
    __shared__ float sScore[128];
    int tid = threadIdx.x;
    int lane = tid & 31, w = tid >> 5;
    int warpM = w >> 1, warpN = w & 1;
    int gid = lane >> 2, qid = lane & 3;
    int rowBase = blockIdx.x << 7;
    if (tid < 128) sScore[tid] = 0.f;

    float acc[2][8][4];
#pragma unroll
    for (int mt=0;mt<2;mt++)
#pragma unroll
        for (int nt=0;nt<8;nt++)
#pragma unroll
            for (int j=0;j<4;j++) acc[mt][nt][j]=0.f;

    for (int kk=0; kk<64; kk+=16){
        if (kk) __syncthreads();
        // A chunk: 128 rows x 16 k, hi/lo split
#pragma unroll
        for (int r=0;r<2;r++){
            int f = tid + (r<<8);
            int row = f>>2, kc4 = (f&3)<<2;
            float4 v = make_float4(0.f,0.f,0.f,0.f);
            int gr = rowBase + row;
            if (gr < N) v = *(const float4*)(A + (size_t)gr*64 + kk + kc4);
            int o = row*20 + kc4;
            float vv[4] = {v.x,v.y,v.z,v.w};
#pragma unroll
            for (int c=0;c<4;c++){
                float hf = __uint_as_float(f2tf(vv[c]));
                sAhi[o+c] = hf;
                sAlo[o+c] = __uint_as_float(f2tf(vv[c]-hf));
            }
        }
        // B chunk: 16 k x 128 cols, hi/lo split
#pragma unroll
        for (int r=0;r<2;r++){
            int f = tid + (r<<8);
            int kr = f>>5, c4 = (f&31)<<2;
            float4 v = *(const float4*)(B + (size_t)(kk+kr)*128 + c4);
            int o = kr*132 + c4;
            float vv[4] = {v.x,v.y,v.z,v.w};
#pragma unroll
            for (int c=0;c<4;c++){
                float hf = __uint_as_float(f2tf(vv[c]));
                sBhi[o+c] = hf;
                sBlo[o+c] = __uint_as_float(f2tf(vv[c]-hf));
            }
        }
        __syncthreads();
#pragma unroll
        for (int ks=0; ks<2; ks++){
            int kb = ks<<3;
            unsigned ahi[2][4], alo[2][4];
#pragma unroll
            for (int mt=0;mt<2;mt++){
                int r0 = (warpM<<5) + (mt<<4) + gid;
                ahi[mt][0] = __float_as_uint(sAhi[r0*20 + kb + qid]);
                ahi[mt][1] = __float_as_uint(sAhi[(r0+8)*20 + kb + qid]);
                ahi[mt][2] = __float_as_uint(sAhi[r0*20 + kb + qid + 4]);
                ahi[mt][3] = __float_as_uint(sAhi[(r0+8)*20 + kb + qid + 4]);
                alo[mt][0] = __float_as_uint(sAlo[r0*20 + kb + qid]);
                alo[mt][1] = __float_as_uint(sAlo[(r0+8)*20 + kb + qid]);
                alo[mt][2] = __float_as_uint(sAlo[r0*20 + kb + qid + 4]);
                alo[mt][3] = __float_as_uint(sAlo[(r0+8)*20 + kb + qid + 4]);
            }
#pragma unroll
            for (int nt=0;nt<8;nt++){
                int nc = (warpN<<6) + (nt<<3) + gid;
                unsigned b0h = __float_as_uint(sBhi[(kb+qid)*132 + nc]);
                unsigned b1h = __float_as_uint(sBhi[(kb+qid+4)*132 + nc]);
                unsigned b0l = __float_as_uint(sBlo[(kb+qid)*132 + nc]);
                unsigned b1l = __float_as_uint(sBlo[(kb+qid+4)*132 + nc]);
#pragma unroll
                for (int mt=0;mt<2;mt++){
                    mma_tf32(acc[mt][nt], ahi[mt], b0h, b1h);
                    mma_tf32(acc[mt][nt], ahi[mt], b0l, b1l);
                    mma_tf32(acc[mt][nt], alo[mt], b0h, b1h);
                }
            }
        }
    }
    // epilogue: bias+relu, write outh fp32 + Xh fp16, fused score partials
#pragma unroll
    for (int mt=0;mt<2;mt++){
        int rloc = (warpM<<5) + (mt<<4) + gid;
        int r0 = rowBase + rloc;
        float sp0 = 0.f, sp8 = 0.f;
#pragma unroll
        for (int nt=0;nt<8;nt++){
            int col = (warpN<<6) + (nt<<3) + (qid<<1);
            float bb0 = __ldg(bias+col), bb1 = __ldg(bias+col+1);
            float pp0 = __ldg(p+col),    pp1 = __ldg(p+col+1);
            float o0 = fmaxf(acc[mt][nt][0]+bb0, 0.f);
            float o1 = fmaxf(acc[mt][nt][1]+bb1, 0.f);
            float o2 = fmaxf(acc[mt][nt][2]+bb0, 0.f);
            float o3 = fmaxf(acc[mt][nt][3]+bb1, 0.f);
            if (r0 < N){
                *(float2*)(outh + (size_t)r0*256 + 128 + col) = make_float2(o0,o1);
                __half2 hv = __floats2half2_rn(o0,o1);
                *(__half2*)(g_Xh + ((size_t)r0<<7) + col) = hv;
            }
            if (r0+8 < N){
                *(float2*)(outh + (size_t)(r0+8)*256 + 128 + col) = make_float2(o2,o3);
                __half2 hv = __floats2half2_rn(o2,o3);
                *(__half2*)(g_Xh + ((size_t)(r0+8)<<7) + col) = hv;
            }
            sp0 += o0*pp0 + o1*pp1;
            sp8 += o2*pp0 + o3*pp1;
        }
        sp0 += __shfl_xor_sync(0xffffffffu, sp0, 1);
        sp0 += __shfl_xor_sync(0xffffffffu, sp0, 2);
        sp8 += __shfl_xor_sync(0xffffffffu, sp8, 1);
        sp8 += __shfl_xor_sync(0xffffffffu, sp8, 2);
        if (qid == 0){
            atomicAdd(&sScore[rloc],   sp0);
            atomicAdd(&sScore[rloc+8], sp8);
        }
    }
    __syncthreads();
    if (tid < 128){
        int gr = rowBase + tid;
        if (gr < N){
            float sc = tanhf(sScore[tid] * g_pinv);
            unsigned u = __float_as_uint(sc);
            unsigned ord = (u & 0x80000000u) ? ~u : (u | 0x80000000u);
            g_keys[gr] = ((ull)ord << 32) | (ull)(0xFFFFFFFFu - (unsigned)gr);
        }
    }
}

// ---- FAT2: blocks [0,nbS) = chunk_sort; rest = CSR fill --------------------
__global__ __launch_bounds__(256) void fat2(const void* __restrict__ edge, int E, int N, int nbS){
    if (blockIdx.x >= nbS){
        int e = (blockIdx.x - nbS)*256 + threadIdx.x;
        if (e < E){
            int r = edge_at(edge,(size_t)e);
            int c = edge_at(edge,(size_t)E+e);
            int pos = atomicAdd(&g_cur[c],1);
            g_rows[pos] = r;
        }
        return;
    }
    __shared__ ull s[128];
    int i = threadIdx.x;
    if (i < 128){
        int g = (blockIdx.x<<7) + i;
        s[i] = (g < N) ? g_keys[g] : 0ULL;
    }
    __syncthreads();
    for (int k=2;k<=128;k<<=1){
        for (int j=k>>1;j>0;j>>=1){
            ull x=0, y=0; int pi = i ^ j;
            if (i < 128){ x = s[i]; y = s[pi]; }
            __syncthreads();
            if (i < 128){
                bool desc = ((i & k) == 0);
                ull keep;
                if (i < pi) keep = desc ? (x>y?x:y) : (x<y?x:y);
                else        keep = desc ? (x<y?x:y) : (x>y?x:y);
                s[i] = keep;
            }
            __syncthreads();
        }
    }
    if (i < 128) g_candA[(blockIdx.x<<7)+i] = s[i];
}

// ---- topk_merge4 (verified) -------------------------------------------------
__global__ void topk_merge4(int M, int srcIsA){
    const ull* src = srcIsA ? g_candA : g_candB;
    ull*       dst = srcIsA ? g_candB : g_candA;
    __shared__ ull s[256];
    int b = blockIdx.x, t = threadIdx.x;
    int half = t>>7, i = t&127;
    int l0 = 4*b + 2*half, l1 = l0+1;
    ull a  = (l0<M) ? src[(l0<<7)+i]        : 0ULL;
    ull bb = (l1<M) ? src[(l1<<7)+(127-i)]  : 0ULL;
    s[t] = (a > bb) ? a : bb;
    __syncthreads();
    for (int j=64;j>0;j>>=1){
        int pi = t ^ j;
        ull x = s[t], y = s[pi];
        __syncthreads();
        s[t] = (t < pi) ? (x>y?x:y) : (x<y?x:y);
        __syncthreads();
    }
    ull fa = s[t];
    ull fb = s[255 - t];
    __syncthreads();
    if (t < 128) s[t] = (fa > fb) ? fa : fb;
    __syncthreads();
    for (int j=64;j>0;j>>=1){
        int pi = t ^ j;
        ull x = s[t], y = s[pi];
        __syncthreads();
        if (t < 128) s[t] = (t < pi) ? (x>y?x:y) : (x<y?x:y);
        __syncthreads();
    }
    if (t < 128) dst[(b<<7)+t] = s[t];
}

// ---- fp16 row load ----------------------------------------------------------
__device__ __forceinline__ float4 ldrow_h(int r, int lane){
    uint2 u = __ldg((const uint2*)(g_Xh + ((size_t)r<<7)) + lane);
    __half2 h0 = *reinterpret_cast<__half2*>(&u.x);
    __half2 h1 = *reinterpret_cast<__half2*>(&u.y);
    float2 f0 = __half22float2(h0), f1 = __half22float2(h1);
    return make_float4(f0.x, f0.y, f1.x, f1.y);
}

// ---- FAT3: blocks [0,128) = GRU; blocks >= 128 = CSR gather (verified R15) -
__global__ __launch_bounds__(256) void fat3(int finalIsA, const float* __restrict__ outh,
                                            const float* __restrict__ W_ih,
                                            const float* __restrict__ W_hh,
                                            const float* __restrict__ b_ih,
                                            const float* __restrict__ b_hh,
                                            const float* __restrict__ h0, int N){
    int tid = threadIdx.x;
    int w = tid>>5, lane = tid&31;
    if (blockIdx.x >= 128){
        int c = (int)(blockIdx.x - 128)*8 + w;
        if (c >= N) return;
        int beg = g_off[c], end = g_off[c+1];
        float dc = g_dinv[c];
        float4 a0 = ldrow_h(c, lane);
        a0.x*=dc; a0.y*=dc; a0.z*=dc; a0.w*=dc;
        float4 a1 = make_float4(0.f,0.f,0.f,0.f);
        float4 a2 = make_float4(0.f,0.f,0.f,0.f);
        float4 a3 = make_float4(0.f,0.f,0.f,0.f);
        int k = beg;
        for (; k+4 <= end; k += 4){
            int r0 = g_rows[k],   r1 = g_rows[k+1];
            int r2 = g_rows[k+2], r3 = g_rows[k+3];
            float d0 = g_dinv[r0], d1 = g_dinv[r1], d2 = g_dinv[r2], d3 = g_dinv[r3];
            float4 v0 = ldrow_h(r0, lane);
            float4 v1 = ldrow_h(r1, lane);
            float4 v2 = ldrow_h(r2, lane);
            float4 v3 = ldrow_h(r3, lane);
            a0.x+=d0*v0.x; a0.y+=d0*v0.y; a0.z+=d0*v0.z; a0.w+=d0*v0.w;
            a1.x+=d1*v1.x; a1.y+=d1*v1.y; a1.z+=d1*v1.z; a1.w+=d1*v1.w;
            a2.x+=d2*v2.x; a2.y+=d2*v2.y; a2.z+=d2*v2.z; a2.w+=d2*v2.w;
            a3.x+=d3*v3.x; a3.y+=d3*v3.y; a3.z+=d3*v3.z; a3.w+=d3*v3.w;
        }
        for (; k < end; k++){
            int r0 = g_rows[k];
            float d0 = g_dinv[r0];
            float4 v0 = ldrow_h(r0, lane);
            a0.x+=d0*v0.x; a0.y+=d0*v0.y; a0.z+=d0*v0.z; a0.w+=d0*v0.w;
        }
        float4 r;
        r.x = dc*((a0.x+a1.x)+(a2.x+a3.x)); r.y = dc*((a0.y+a1.y)+(a2.y+a3.y));
        r.z = dc*((a0.z+a1.z)+(a2.z+a3.z)); r.w = dc*((a0.w+a1.w)+(a2.w+a3.w));
        *((float4*)(g_AX + ((size_t)c<<7)) + lane) = r;
        return;
    }
    __shared__ __align__(16) float xt[128];
    __shared__ __align__(16) float hr[128];
    __shared__ float gi[384];
    __shared__ float gh[384];
    int kk = blockIdx.x;
    const ull* top = finalIsA ? g_candA : g_candB;
    ull key = top[kk];
    unsigned idx = 0xFFFFFFFFu - (unsigned)(key & 0xFFFFFFFFull);
    unsigned ord = (unsigned)(key >> 32);
    unsigned u = (ord & 0x80000000u) ? (ord & 0x7FFFFFFFu) : ~ord;
    float val = __uint_as_float(u);
    if (tid < 128){
        xt[tid] = outh[(size_t)idx*256 + 128 + tid] * val;
        hr[tid] = h0[(kk<<7) + tid];
    }
    __syncthreads();
    for (int d = w; d < 768; d += 8){
        int isH = (d >= 384);
        int j = isH ? d - 384 : d;
        const float* W = isH ? W_hh : W_ih;
        const float* src = isH ? hr : xt;
        float4 wv = __ldg((const float4*)(W + (j<<7)) + lane);
        float4 sv = ((const float4*)src)[lane];
        float s = wv.x*sv.x + wv.y*sv.y + wv.z*sv.z + wv.w*sv.w;
#pragma unroll
        for (int m=16;m>0;m>>=1) s += __shfl_xor_sync(0xffffffffu, s, m);
        if (lane==0){
            s += isH ? b_hh[j] : b_ih[j];
            (isH ? gh : gi)[j] = s;
        }
    }
    __syncthreads();
    if (tid < 128){
        float r = 1.f/(1.f + expf(-(gi[tid]+gh[tid])));
        float z = 1.f/(1.f + expf(-(gi[tid+128]+gh[tid+128])));
        float nn = tanhf(gi[tid+256] + r*gh[tid+256]);
        g_wev[(kk<<7)+tid] = (1.f - z)*nn + z*hr[tid];
    }
}

// ---- GEMM2 (tf32 MMA, verified): g_AX@g_wev -> outh[:,0:128] ---------------
__global__ __launch_bounds__(256) void gemm2_mma(float* __restrict__ outh, int N){
    __shared__ unsigned sA[128*33];
    __shared__ unsigned sB[32*132];
    int tid = threadIdx.x;
    int lane = tid & 31, w = tid >> 5;
    int warpM = w >> 1, warpN = w & 1;
    int rowBase = blockIdx.x << 7;
    int gid = lane >> 2, qid = lane & 3;

    float acc[2][8][4];
#pragma unroll
    for (int mt=0;mt<2;mt++)
#pragma unroll
        for (int nt=0;nt<8;nt++)
#pragma unroll
            for (int j=0;j<4;j++) acc[mt][nt][j]=0.f;

    for (int kk=0; kk<128; kk+=32){
#pragma unroll
        for (int r=0;r<4;r++){
            int f = tid + (r<<8);
            int row = f>>3, kc4 = f&7;
            float4 v = make_float4(0.f,0.f,0.f,0.f);
            int gr = rowBase + row;
            if (gr < N) v = *(const float4*)(g_AX + ((size_t)gr<<7) + kk + (kc4<<2));
            int o = row*33 + (kc4<<2);
            sA[o]=f2tf(v.x); sA[o+1]=f2tf(v.y); sA[o+2]=f2tf(v.z); sA[o+3]=f2tf(v.w);
        }
#pragma unroll
        for (int r=0;r<4;r++){
            int f = tid + (r<<8);
            int kr = f>>5, c4 = f&31;
            float4 v = *(const float4*)(g_wev + (size_t)(kk+kr)*128 + (c4<<2));
            int o = kr*132 + (c4<<2);
            sB[o]=f2tf(v.x); sB[o+1]=f2tf(v.y); sB[o+2]=f2tf(v.z); sB[o+3]=f2tf(v.w);
        }
        __syncthreads();
#pragma unroll
        for (int ks=0; ks<4; ks++){
            int kb = ks<<3;
            unsigned a[2][4];
#pragma unroll
            for (int mt=0;mt<2;mt++){
                int r0 = (warpM<<5) + (mt<<4) + gid;
                a[mt][0] = sA[r0*33 + kb + qid];
                a[mt][1] = sA[(r0+8)*33 + kb + qid];
                a[mt][2] = sA[r0*33 + kb + qid + 4];
                a[mt][3] = sA[(r0+8)*33 + kb + qid + 4];
            }
#pragma unroll
            for (int nt=0;nt<8;nt++){
                int nc = (warpN<<6) + (nt<<3) + gid;
                unsigned b0 = sB[(kb + qid)*132 + nc];
                unsigned b1 = sB[(kb + qid + 4)*132 + nc];
                mma_tf32(acc[0][nt], a[0], b0, b1);
                mma_tf32(acc[1][nt], a[1], b0, b1);
            }
        }
        __syncthreads();
    }
#pragma unroll
    for (int mt=0;mt<2;mt++){
        int r0 = rowBase + (warpM<<5) + (mt<<4) + gid;
#pragma unroll
        for (int nt=0;nt<8;nt++){
            int col = (warpN<<6) + (nt<<3) + (qid<<1);
            if (r0 < N)   *(float2*)(outh + (size_t)r0*256 + col)     = make_float2(acc[mt][nt][0], acc[mt][nt][1]);
            if (r0+8 < N) *(float2*)(outh + (size_t)(r0+8)*256 + col) = make_float2(acc[mt][nt][2], acc[mt][nt][3]);
        }
    }
}

// ---- final (tf32 MMA, verified): q = h@W2 + b2 -----------------------------
__global__ __launch_bounds__(256) void final_mma(const float* __restrict__ W2,
                                                 const float* __restrict__ b2,
                                                 float* __restrict__ outq,
                                                 const float* __restrict__ outh, int N){
    __shared__ unsigned sA[128*33];
    __shared__ unsigned sW[256*17];
    int tid = threadIdx.x;
    int lane = tid & 31, w = tid >> 5;
    int gid = lane >> 2, qid = lane & 3;
    int rowBase = blockIdx.x << 7;

    for (int i=tid;i<4096;i+=256){
        int kr = i >> 4, c = i & 15;
        sW[kr*17 + c] = f2tf(W2[i]);
    }
    float acc[2][4];
#pragma unroll
    for (int nt=0;nt<2;nt++)
#pragma unroll
        for (int j=0;j<4;j++) acc[nt][j]=0.f;

    for (int kk=0; kk<256; kk+=32){
#pragma unroll
        for (int r=0;r<4;r++){
            int f = tid + (r<<8);
            int row = f>>3, kc4 = f&7;
            float4 v = make_float4(0.f,0.f,0.f,0.f);
            int gr = rowBase + row;
            if (gr < N) v = *(const float4*)(outh + (size_t)gr*256 + kk + (kc4<<2));
            int o = row*33 + (kc4<<2);
            sA[o]=f2tf(v.x); sA[o+1]=f2tf(v.y); sA[o+2]=f2tf(v.z); sA[o+3]=f2tf(v.w);
        }
        __syncthreads();
#pragma unroll
        for (int ks=0; ks<4; ks++){
            int kb = ks<<3;
            int r0 = (w<<4) + gid;
            unsigned a[4];
            a[0] = sA[r0*33 + kb + qid];
            a[1] = sA[(r0+8)*33 + kb + qid];
            a[2] = sA[r0*33 + kb + qid + 4];
            a[3] = sA[(r0+8)*33 + kb + qid + 4];
#pragma unroll
            for (int nt=0;nt<2;nt++){
                unsigned b0 = sW[(kk+kb+qid)*17 + (nt<<3) + gid];
                unsigned b1 = sW[(kk+kb+qid+4)*17 + (nt<<3) + gid];
                mma_tf32(acc[nt], a, b0, b1);
            }
        }
        __syncthreads();
    }
    int r0 = rowBase + (w<<4) + gid;
#pragma unroll
    for (int nt=0;nt<2;nt++){
        int col = (nt<<3) + (qid<<1);
        float c0 = __ldg(b2+col), c1 = __ldg(b2+col+1);
        if (r0 < N)   *(float2*)(outq + (size_t)r0*16 + col)     = make_float2(acc[nt][0]+c0, acc[nt][1]+c1);
        if (r0+8 < N) *(float2*)(outq + (size_t)(r0+8)*16 + col) = make_float2(acc[nt][2]+c0, acc[nt][3]+c1);
    }
}

extern "C" void kernel_launch(void* const* d_in, const int* in_sizes, int n_in,
                              void* d_out, int out_size) {
    const float* inputs = (const float*)d_in[0];
    const void*  edge   = d_in[2];
    const float* W1     = (const float*)d_in[3];
    const float* b1     = (const float*)d_in[4];
    const float* p      = (const float*)d_in[5];
    const float* W_ih   = (const float*)d_in[6];
    const float* W_hh   = (const float*)d_in[7];
    const float* b_ih   = (const float*)d_in[8];
    const float* b_hh   = (const float*)d_in[9];
    const float* iw     = (const float*)d_in[10];
    const float* W2     = (const float*)d_in[11];
    const float* b2     = (const float*)d_in[12];

    int N = in_sizes[0] / 64;
    int E = in_sizes[2] / 2;
    float* outq = (float*)d_out;
    float* outh = (float*)d_out + (size_t)N*16;

    int nb128  = (N + 127) / 128;
    int nbScan = (N + 511) / 512;
    int nbE    = (E + 255) / 256;
    int nbGath = (N + 7) / 8;

    setup_zero<<<(N+255)/256,256>>>(edge, p, N);
    fat1<<<nb128 + nbE, 256>>>(inputs, W1, b1, p, outh, edge, N, E, nb128);
    scan1<<<nbScan,512>>>(N);
    scan2<<<1,256>>>(nbScan);
    scan3<<<(N+255)/256,256>>>(N, E);
    fat2<<<nb128 + nbE, 256>>>(edge, E, N, nb128);
    int M = nb128, srcA = 1;
    while (M > 1){
        int nb = (M+3)/4;
        topk_merge4<<<nb,256>>>(M, srcA);
        M = nb; srcA ^= 1;
    }
    fat3<<<128 + nbGath, 256>>>(srcA, outh, W_ih, W_hh, b_ih, b_hh, iw, N);
    gemm2_mma<<<nb128,256>>>(outh, N);
    final_mma<<<nb128,256>>>(W2, b2, outq, outh, N);
}

// round 17
// speedup vs baseline: 1.1117x; 1.1117x over previous
#include <cuda_runtime.h>
#include <cuda_fp16.h>
#include <cstdint>

typedef unsigned long long ull;
#define MAXN 100096
#define MAXE 1700000

__device__ float  g_AX[MAXN*128];
__device__ __half g_Xh[MAXN*128];
__device__ ull    g_keys [MAXN];
__device__ ull    g_candA[MAXN];
__device__ ull    g_candB[MAXN];
__device__ float  g_wev[128*128];
__device__ float  g_dinv[MAXN];
__device__ int    g_cnt [MAXN];
__device__ int    g_off [MAXN+1];
__device__ int    g_cur [MAXN];
__device__ int    g_rows[MAXE];
__device__ int    g_bsum[256];
__device__ float  g_pinv;
__device__ int    g_e64;

__device__ __forceinline__ int edge_at(const void* edge, size_t idx){
    return g_e64 ? ((const int*)edge)[2*idx] : ((const int*)edge)[idx];
}

// ---- setup (pnorm + dtype detect) fused with cnt zeroing -------------------
__global__ void setup_zero(const void* __restrict__ edge, const float* __restrict__ p, int N){
    __shared__ float s[128];
    int i = blockIdx.x*256 + threadIdx.x;
    if (i < N) g_cnt[i] = 0;
    if (blockIdx.x == 0){
        int t = threadIdx.x;
        if (t < 128){ float v = p[t]; s[t] = v*v; }
        __syncthreads();
        for (int o=64;o>0;o>>=1){ if (t<o) s[t]+=s[t+o]; __syncthreads(); }
        if (t==0){
            g_pinv = rsqrtf(s[0]);
            const long long* e = (const long long*)edge;
            int ok = 1;
            for (int k=0;k<8;k++){ long long vv=e[k]; if (vv<0 || vv>=(long long)N) ok=0; }
            g_e64 = ok;
        }
    }
}

// ---- scan1 -----------------------------------------------------------------
__global__ void scan1(int N){
    __shared__ int s[512];
    int t = threadIdx.x;
    int i = blockIdx.x*512 + t;
    int v = (i<N) ? g_cnt[i] : 0;
    if (i<N) g_dinv[i] = rsqrtf((float)(v+1));
    s[t]=v; __syncthreads();
    for (int o=1;o<512;o<<=1){
        int tmp = (t>=o)? s[t-o] : 0; __syncthreads();
        s[t]+=tmp; __syncthreads();
    }
    if (i<N) g_off[i] = s[t]-v;
    if (t==511) g_bsum[blockIdx.x] = s[511];
}

// ---- scan3f: fused block-sum scan + apply (verified R11/R12/R13) -----------
__global__ void scan3f(int N, int E, int nb){
    __shared__ int s[256];
    __shared__ int ex[256];
    int t = threadIdx.x;
    int v = (t<nb)? g_bsum[t] : 0;
    s[t]=v; __syncthreads();
    for (int o=1;o<256;o<<=1){
        int tmp=(t>=o)?s[t-o]:0; __syncthreads();
        s[t]+=tmp; __syncthreads();
    }
    ex[t] = s[t]-v; __syncthreads();
    int i = blockIdx.x*256 + t;
    if (i<N){
        int vv = g_off[i] + ex[i>>9];
        g_off[i]=vv; g_cur[i]=vv;
    }
    if (i==0) g_off[N]=E;
}

// ---- FAT1: blocks [0,nbG) = GEMM1 (fp32, feeds top-k); rest = cnt_count ----
__global__ __launch_bounds__(256) void fat1(const float* __restrict__ A,
                                            const float* __restrict__ B,
                                            const float* __restrict__ bias,
                                            const float* __restrict__ p,
                                            float* __restrict__ outh,
                                            const void* __restrict__ edge,
                                            int N, int E, int nbG){
    if (blockIdx.x >= nbG){
        int e = (blockIdx.x - nbG)*256 + threadIdx.x;
        if (e < E) atomicAdd(&g_cnt[edge_at(edge,(size_t)E+e)],1);
        return;
    }
    const int K = 64;
    __shared__ float sA[128*33];
    __shared__ float sW[32*132];
    int tid = threadIdx.x;
    int tx = tid & 15, ty = tid >> 4;
    int rowBase = blockIdx.x << 7;
    float acc[8][8];
#pragma unroll
    for (int i=0;i<8;i++)
#pragma unroll
        for (int j=0;j<8;j++) acc[i][j]=0.f;

    for (int kk=0; kk<K; kk+=32){
#pragma unroll
        for (int r=0;r<4;r++){
            int f = tid + (r<<8);
            int row = f>>3, kc4 = f&7;
            float4 v = make_float4(0.f,0.f,0.f,0.f);
            int gr = rowBase + row;
            if (gr < N) v = *(const float4*)(A + (size_t)gr*K + kk + (kc4<<2));
            int o = row*33 + (kc4<<2);
            sA[o]=v.x; sA[o+1]=v.y; sA[o+2]=v.z; sA[o+3]=v.w;
        }
#pragma unroll
        for (int r=0;r<4;r++){
            int f = tid + (r<<8);
            int kr = f>>5, c4 = f&31;
            *(float4*)&sW[kr*132 + (c4<<2)] = *(const float4*)(B + (size_t)(kk+kr)*128 + (c4<<2));
        }
        __syncthreads();
#pragma unroll 8
        for (int kc=0;kc<32;kc++){
            float a[8];
#pragma unroll
            for (int i=0;i<8;i++) a[i] = sA[(ty + (i<<4))*33 + kc];
            float4 w0 = *(const float4*)&sW[kc*132 + (tx<<3)];
            float4 w1 = *(const float4*)&sW[kc*132 + (tx<<3) + 4];
#pragma unroll
            for (int i=0;i<8;i++){
                acc[i][0]+=a[i]*w0.x; acc[i][1]+=a[i]*w0.y; acc[i][2]+=a[i]*w0.z; acc[i][3]+=a[i]*w0.w;
                acc[i][4]+=a[i]*w1.x; acc[i][5]+=a[i]*w1.y; acc[i][6]+=a[i]*w1.z; acc[i][7]+=a[i]*w1.w;
            }
        }
        __syncthreads();
    }
    float bj[8], pv[8];
#pragma unroll
    for (int j=0;j<8;j++){
        bj[j] = bias[(tx<<3)+j];
        pv[j] = p[(tx<<3)+j];
    }
#pragma unroll
    for (int i=0;i<8;i++){
        int gr = rowBase + ty + (i<<4);
        bool ok = (gr < N);
        float o[8];
#pragma unroll
        for (int j=0;j<8;j++) o[j] = fmaxf(acc[i][j] + bj[j], 0.f);
        if (ok){
            float* cp = outh + (size_t)gr*256 + 128 + (tx<<3);
            *(float4*)cp       = make_float4(o[0],o[1],o[2],o[3]);
            *(float4*)(cp + 4) = make_float4(o[4],o[5],o[6],o[7]);
            __half2 p01=__floats2half2_rn(o[0],o[1]);
            __half2 p23=__floats2half2_rn(o[2],o[3]);
            __half2 p45=__floats2half2_rn(o[4],o[5]);
            __half2 p67=__floats2half2_rn(o[6],o[7]);
            uint4 hv = make_uint4(*(unsigned*)&p01, *(unsigned*)&p23,
                                  *(unsigned*)&p45, *(unsigned*)&p67);
            *(uint4*)(g_Xh + ((size_t)gr<<7) + (tx<<3)) = hv;
        }
        float dot = 0.f;
#pragma unroll
        for (int j=0;j<8;j++) dot += o[j]*pv[j];
#pragma unroll
        for (int m=1;m<16;m<<=1) dot += __shfl_xor_sync(0xffffffffu, dot, m);
        if (tx==0 && ok){
            float sc = tanhf(dot * g_pinv);
            unsigned u = __float_as_uint(sc);
            unsigned ord = (u & 0x80000000u) ? ~u : (u | 0x80000000u);
            g_keys[gr] = ((ull)ord << 32) | (ull)(0xFFFFFFFFu - (unsigned)gr);
        }
    }
}

// ---- FAT2: blocks [0,nbS) = chunk_sort; rest = CSR fill --------------------
__global__ __launch_bounds__(256) void fat2(const void* __restrict__ edge, int E, int N, int nbS){
    if (blockIdx.x >= nbS){
        int e = (blockIdx.x - nbS)*256 + threadIdx.x;
        if (e < E){
            int r = edge_at(edge,(size_t)e);
            int c = edge_at(edge,(size_t)E+e);
            int pos = atomicAdd(&g_cur[c],1);
            g_rows[pos] = r;
        }
        return;
    }
    __shared__ ull s[128];
    int i = threadIdx.x;
    if (i < 128){
        int g = (blockIdx.x<<7) + i;
        s[i] = (g < N) ? g_keys[g] : 0ULL;
    }
    __syncthreads();
    for (int k=2;k<=128;k<<=1){
        for (int j=k>>1;j>0;j>>=1){
            ull x=0, y=0; int pi = i ^ j;
            if (i < 128){ x = s[i]; y = s[pi]; }
            __syncthreads();
            if (i < 128){
                bool desc = ((i & k) == 0);
                ull keep;
                if (i < pi) keep = desc ? (x>y?x:y) : (x<y?x:y);
                else        keep = desc ? (x<y?x:y) : (x>y?x:y);
                s[i] = keep;
            }
            __syncthreads();
        }
    }
    if (i < 128) g_candA[(blockIdx.x<<7)+i] = s[i];
}

// ---- topk_merge4 (verified) -------------------------------------------------
__global__ void topk_merge4(int M, int srcIsA){
    const ull* src = srcIsA ? g_candA : g_candB;
    ull*       dst = srcIsA ? g_candB : g_candA;
    __shared__ ull s[256];
    int b = blockIdx.x, t = threadIdx.x;
    int half = t>>7, i = t&127;
    int l0 = 4*b + 2*half, l1 = l0+1;
    ull a  = (l0<M) ? src[(l0<<7)+i]        : 0ULL;
    ull bb = (l1<M) ? src[(l1<<7)+(127-i)]  : 0ULL;
    s[t] = (a > bb) ? a : bb;
    __syncthreads();
    for (int j=64;j>0;j>>=1){
        int pi = t ^ j;
        ull x = s[t], y = s[pi];
        __syncthreads();
        s[t] = (t < pi) ? (x>y?x:y) : (x<y?x:y);
        __syncthreads();
    }
    ull fa = s[t];
    ull fb = s[255 - t];
    __syncthreads();
    if (t < 128) s[t] = (fa > fb) ? fa : fb;
    __syncthreads();
    for (int j=64;j>0;j>>=1){
        int pi = t ^ j;
        ull x = s[t], y = s[pi];
        __syncthreads();
        if (t < 128) s[t] = (t < pi) ? (x>y?x:y) : (x<y?x:y);
        __syncthreads();
    }
    if (t < 128) dst[(b<<7)+t] = s[t];
}

// ---- fp16 row load ----------------------------------------------------------
__device__ __forceinline__ float4 ldrow_h(int r, int lane){
    uint2 u = __ldg((const uint2*)(g_Xh + ((size_t)r<<7)) + lane);
    __half2 h0 = *reinterpret_cast<__half2*>(&u.x);
    __half2 h1 = *reinterpret_cast<__half2*>(&u.y);
    float2 f0 = __half22float2(h0), f1 = __half22float2(h1);
    return make_float4(f0.x, f0.y, f1.x, f1.y);
}

// ---- FAT3: blocks [0,128) = GRU; blocks >= 128 = CSR gather (verified R15) -
__global__ __launch_bounds__(256) void fat3(int finalIsA, const float* __restrict__ outh,
                                            const float* __restrict__ W_ih,
                                            const float* __restrict__ W_hh,
                                            const float* __restrict__ b_ih,
                                            const float* __restrict__ b_hh,
                                            const float* __restrict__ h0, int N){
    int tid = threadIdx.x;
    int w = tid>>5, lane = tid&31;
    if (blockIdx.x >= 128){
        int c = (int)(blockIdx.x - 128)*8 + w;
        if (c >= N) return;
        int beg = g_off[c], end = g_off[c+1];
        float dc = g_dinv[c];
        float4 a0 = ldrow_h(c, lane);
        a0.x*=dc; a0.y*=dc; a0.z*=dc; a0.w*=dc;
        float4 a1 = make_float4(0.f,0.f,0.f,0.f);
        float4 a2 = make_float4(0.f,0.f,0.f,0.f);
        float4 a3 = make_float4(0.f,0.f,0.f,0.f);
        int k = beg;
        for (; k+4 <= end; k += 4){
            int r0 = g_rows[k],   r1 = g_rows[k+1];
            int r2 = g_rows[k+2], r3 = g_rows[k+3];
            float d0 = g_dinv[r0], d1 = g_dinv[r1], d2 = g_dinv[r2], d3 = g_dinv[r3];
            float4 v0 = ldrow_h(r0, lane);
            float4 v1 = ldrow_h(r1, lane);
            float4 v2 = ldrow_h(r2, lane);
            float4 v3 = ldrow_h(r3, lane);
            a0.x+=d0*v0.x; a0.y+=d0*v0.y; a0.z+=d0*v0.z; a0.w+=d0*v0.w;
            a1.x+=d1*v1.x; a1.y+=d1*v1.y; a1.z+=d1*v1.z; a1.w+=d1*v1.w;
            a2.x+=d2*v2.x; a2.y+=d2*v2.y; a2.z+=d2*v2.z; a2.w+=d2*v2.w;
            a3.x+=d3*v3.x; a3.y+=d3*v3.y; a3.z+=d3*v3.z; a3.w+=d3*v3.w;
        }
        for (; k < end; k++){
            int r0 = g_rows[k];
            float d0 = g_dinv[r0];
            float4 v0 = ldrow_h(r0, lane);
            a0.x+=d0*v0.x; a0.y+=d0*v0.y; a0.z+=d0*v0.z; a0.w+=d0*v0.w;
        }
        float4 r;
        r.x = dc*((a0.x+a1.x)+(a2.x+a3.x)); r.y = dc*((a0.y+a1.y)+(a2.y+a3.y));
        r.z = dc*((a0.z+a1.z)+(a2.z+a3.z)); r.w = dc*((a0.w+a1.w)+(a2.w+a3.w));
        *((float4*)(g_AX + ((size_t)c<<7)) + lane) = r;
        return;
    }
    __shared__ __align__(16) float xt[128];
    __shared__ __align__(16) float hr[128];
    __shared__ float gi[384];
    __shared__ float gh[384];
    int kk = blockIdx.x;
    const ull* top = finalIsA ? g_candA : g_candB;
    ull key = top[kk];
    unsigned idx = 0xFFFFFFFFu - (unsigned)(key & 0xFFFFFFFFull);
    unsigned ord = (unsigned)(key >> 32);
    unsigned u = (ord & 0x80000000u) ? (ord & 0x7FFFFFFFu) : ~ord;
    float val = __uint_as_float(u);
    if (tid < 128){
        xt[tid] = outh[(size_t)idx*256 + 128 + tid] * val;
        hr[tid] = h0[(kk<<7) + tid];
    }
    __syncthreads();
    for (int d = w; d < 768; d += 8){
        int isH = (d >= 384);
        int j = isH ? d - 384 : d;
        const float* W = isH ? W_hh : W_ih;
        const float* src = isH ? hr : xt;
        float4 wv = __ldg((const float4*)(W + (j<<7)) + lane);
        float4 sv = ((const float4*)src)[lane];
        float s = wv.x*sv.x + wv.y*sv.y + wv.z*sv.z + wv.w*sv.w;
#pragma unroll
        for (int m=16;m>0;m>>=1) s += __shfl_xor_sync(0xffffffffu, s, m);
        if (lane==0){
            s += isH ? b_hh[j] : b_ih[j];
            (isH ? gh : gi)[j] = s;
        }
    }
    __syncthreads();
    if (tid < 128){
        float r = 1.f/(1.f + expf(-(gi[tid]+gh[tid])));
        float z = 1.f/(1.f + expf(-(gi[tid+128]+gh[tid+128])));
        float nn = tanhf(gi[tid+256] + r*gh[tid+256]);
        g_wev[(kk<<7)+tid] = (1.f - z)*nn + z*hr[tid];
    }
}

// ---- tf32 helpers ----------------------------------------------------------
__device__ __forceinline__ unsigned f2tf(float x){
    unsigned r; asm("cvt.rna.tf32.f32 %0, %1;" : "=r"(r) : "f"(x)); return r;
}
__device__ __forceinline__ void mma_tf32(float* c, const unsigned* a, unsigned b0, unsigned b1){
    asm volatile("mma.sync.aligned.m16n8k8.row.col.f32.tf32.tf32.f32 "
        "{%0,%1,%2,%3},{%4,%5,%6,%7},{%8,%9},{%0,%1,%2,%3};"
        : "+f"(c[0]),"+f"(c[1]),"+f"(c[2]),"+f"(c[3])
        : "r"(a[0]),"r"(a[1]),"r"(a[2]),"r"(a[3]), "r"(b0),"r"(b1));
}

// ---- GEMM2 (tf32 MMA, verified): g_AX@g_wev -> outh[:,0:128] ---------------
__global__ __launch_bounds__(256) void gemm2_mma(float* __restrict__ outh, int N){
    __shared__ unsigned sA[128*33];
    __shared__ unsigned sB[32*132];
    int tid = threadIdx.x;
    int lane = tid & 31, w = tid >> 5;
    int warpM = w >> 1, warpN = w & 1;
    int rowBase = blockIdx.x << 7;
    int gid = lane >> 2, qid = lane & 3;

    float acc[2][8][4];
#pragma unroll
    for (int mt=0;mt<2;mt++)
#pragma unroll
        for (int nt=0;nt<8;nt++)
#pragma unroll
            for (int j=0;j<4;j++) acc[mt][nt][j]=0.f;

    for (int kk=0; kk<128; kk+=32){
#pragma unroll
        for (int r=0;r<4;r++){
            int f = tid + (r<<8);
            int row = f>>3, kc4 = f&7;
            float4 v = make_float4(0.f,0.f,0.f,0.f);
            int gr = rowBase + row;
            if (gr < N) v = *(const float4*)(g_AX + ((size_t)gr<<7) + kk + (kc4<<2));
            int o = row*33 + (kc4<<2);
            sA[o]=f2tf(v.x); sA[o+1]=f2tf(v.y); sA[o+2]=f2tf(v.z); sA[o+3]=f2tf(v.w);
        }
#pragma unroll
        for (int r=0;r<4;r++){
            int f = tid + (r<<8);
            int kr = f>>5, c4 = f&31;
            float4 v = *(const float4*)(g_wev + (size_t)(kk+kr)*128 + (c4<<2));
            int o = kr*132 + (c4<<2);
            sB[o]=f2tf(v.x); sB[o+1]=f2tf(v.y); sB[o+2]=f2tf(v.z); sB[o+3]=f2tf(v.w);
        }
        __syncthreads();
#pragma unroll
        for (int ks=0; ks<4; ks++){
            int kb = ks<<3;
            unsigned a[2][4];
#pragma unroll
            for (int mt=0;mt<2;mt++){
                int r0 = (warpM<<5) + (mt<<4) + gid;
                a[mt][0] = sA[r0*33 + kb + qid];
                a[mt][1] = sA[(r0+8)*33 + kb + qid];
                a[mt][2] = sA[r0*33 + kb + qid + 4];
                a[mt][3] = sA[(r0+8)*33 + kb + qid + 4];
            }
#pragma unroll
            for (int nt=0;nt<8;nt++){
                int nc = (warpN<<6) + (nt<<3) + gid;
                unsigned b0 = sB[(kb + qid)*132 + nc];
                unsigned b1 = sB[(kb + qid + 4)*132 + nc];
                mma_tf32(acc[0][nt], a[0], b0, b1);
                mma_tf32(acc[1][nt], a[1], b0, b1);
            }
        }
        __syncthreads();
    }
#pragma unroll
    for (int mt=0;mt<2;mt++){
        int r0 = rowBase + (warpM<<5) + (mt<<4) + gid;
#pragma unroll
        for (int nt=0;nt<8;nt++){
            int col = (warpN<<6) + (nt<<3) + (qid<<1);
            if (r0 < N)   *(float2*)(outh + (size_t)r0*256 + col)     = make_float2(acc[mt][nt][0], acc[mt][nt][1]);
            if (r0+8 < N) *(float2*)(outh + (size_t)(r0+8)*256 + col) = make_float2(acc[mt][nt][2], acc[mt][nt][3]);
        }
    }
}

// ---- final (tf32 MMA, verified): q = h@W2 + b2 -----------------------------
__global__ __launch_bounds__(256) void final_mma(const float* __restrict__ W2,
                                                 const float* __restrict__ b2,
                                                 float* __restrict__ outq,
                                                 const float* __restrict__ outh, int N){
    __shared__ unsigned sA[128*33];
    __shared__ unsigned sW[256*17];
    int tid = threadIdx.x;
    int lane = tid & 31, w = tid >> 5;
    int gid = lane >> 2, qid = lane & 3;
    int rowBase = blockIdx.x << 7;

    for (int i=tid;i<4096;i+=256){
        int kr = i >> 4, c = i & 15;
        sW[kr*17 + c] = f2tf(W2[i]);
    }
    float acc[2][4];
#pragma unroll
    for (int nt=0;nt<2;nt++)
#pragma unroll
        for (int j=0;j<4;j++) acc[nt][j]=0.f;

    for (int kk=0; kk<256; kk+=32){
#pragma unroll
        for (int r=0;r<4;r++){
            int f = tid + (r<<8);
            int row = f>>3, kc4 = f&7;
            float4 v = make_float4(0.f,0.f,0.f,0.f);
            int gr = rowBase + row;
            if (gr < N) v = *(const float4*)(outh + (size_t)gr*256 + kk + (kc4<<2));
            int o = row*33 + (kc4<<2);
            sA[o]=f2tf(v.x); sA[o+1]=f2tf(v.y); sA[o+2]=f2tf(v.z); sA[o+3]=f2tf(v.w);
        }
        __syncthreads();
#pragma unroll
        for (int ks=0; ks<4; ks++){
            int kb = ks<<3;
            int r0 = (w<<4) + gid;
            unsigned a[4];
            a[0] = sA[r0*33 + kb + qid];
            a[1] = sA[(r0+8)*33 + kb + qid];
            a[2] = sA[r0*33 + kb + qid + 4];
            a[3] = sA[(r0+8)*33 + kb + qid + 4];
#pragma unroll
            for (int nt=0;nt<2;nt++){
                unsigned b0 = sW[(kk+kb+qid)*17 + (nt<<3) + gid];
                unsigned b1 = sW[(kk+kb+qid+4)*17 + (nt<<3) + gid];
                mma_tf32(acc[nt], a, b0, b1);
            }
        }
        __syncthreads();
    }
    int r0 = rowBase + (w<<4) + gid;
#pragma unroll
    for (int nt=0;nt<2;nt++){
        int col = (nt<<3) + (qid<<1);
        float c0 = __ldg(b2+col), c1 = __ldg(b2+col+1);
        if (r0 < N)   *(float2*)(outq + (size_t)r0*16 + col)     = make_float2(acc[nt][0]+c0, acc[nt][1]+c1);
        if (r0+8 < N) *(float2*)(outq + (size_t)(r0+8)*16 + col) = make_float2(acc[nt][2]+c0, acc[nt][3]+c1);
    }
}

extern "C" void kernel_launch(void* const* d_in, const int* in_sizes, int n_in,
                              void* d_out, int out_size) {
    const float* inputs = (const float*)d_in[0];
    const void*  edge   = d_in[2];
    const float* W1     = (const float*)d_in[3];
    const float* b1     = (const float*)d_in[4];
    const float* p      = (const float*)d_in[5];
    const float* W_ih   = (const float*)d_in[6];
    const float* W_hh   = (const float*)d_in[7];
    const float* b_ih   = (const float*)d_in[8];
    const float* b_hh   = (const float*)d_in[9];
    const float* iw     = (const float*)d_in[10];
    const float* W2     = (const float*)d_in[11];
    const float* b2     = (const float*)d_in[12];

    int N = in_sizes[0] / 64;
    int E = in_sizes[2] / 2;
    float* outq = (float*)d_out;
    float* outh = (float*)d_out + (size_t)N*16;

    int nb128  = (N + 127) / 128;
    int nbScan = (N + 511) / 512;
    int nbE    = (E + 255) / 256;
    int nbGath = (N + 7) / 8;

    setup_zero<<<(N+255)/256,256>>>(edge, p, N);
    fat1<<<nb128 + nbE, 256>>>(inputs, W1, b1, p, outh, edge, N, E, nb128);
    scan1<<<nbScan,512>>>(N);
    scan3f<<<(N+255)/256,256>>>(N, E, nbScan);
    fat2<<<nb128 + nbE, 256>>>(edge, E, N, nb128);
    int M = nb128, srcA = 1;
    while (M > 1){
        int nb = (M+3)/4;
        topk_merge4<<<nb,256>>>(M, srcA);
        M = nb; srcA ^= 1;
    }
    fat3<<<128 + nbGath, 256>>>(srcA, outh, W_ih, W_hh, b_ih, b_hh, iw, N);
    gemm2_mma<<<nb128,256>>>(outh, N);
    final_mma<<<nb128,256>>>(W2, b2, outq, outh, N);
}